// round 1
// baseline (speedup 1.0000x reference)
#include <cuda_runtime.h>
#include <math.h>

// Problem constants
#define Bn 4
#define Sn 2048
#define Hn 512
#define NHn 8
#define DHn 64
#define Fn 2048
#define Ln 4
#define Mn (Bn * Sn)  // 8192

// Scratch (device globals; no allocation allowed)
__device__ float g_x[Mn * Hn];
__device__ float g_q[Mn * Hn];
__device__ float g_k[Mn * Hn];
__device__ float g_v[Mn * Hn];
__device__ float g_ctx[Mn * Hn];
__device__ float g_attn[Mn * Hn];
__device__ float g_ffn[Mn * Fn];
__device__ float g_sc[(size_t)Bn * NHn * Sn * Sn];  // 512 MB scores/probs

// ---------------------------------------------------------------------------
// Generic tiled GEMM: C[M,N] = A[M,K] * W[K,N] + bias (+res / gelu epilogue)
// BM=BN=64, BK=16, 256 threads, 4x4 per thread.
// EPI: 0 = bias only, 1 = bias + residual, 2 = bias then exact GELU
// ---------------------------------------------------------------------------
template <int EPI>
__global__ void __launch_bounds__(256) gemm_kernel(
    const float* __restrict__ A, const float* __restrict__ W,
    const float* __restrict__ bias, const float* __restrict__ res,
    float* __restrict__ C, int K, int N)
{
    __shared__ __align__(16) float As[16][68];
    __shared__ __align__(16) float Ws[16][68];
    const int tid = threadIdx.x;
    const int tx = tid & 15, ty = tid >> 4;
    const int m0 = blockIdx.y << 6, n0 = blockIdx.x << 6;
    const int lam = tid >> 2, lak = (tid & 3) << 2;      // A tile load map
    const int lwk = tid >> 4, lwn = (tid & 15) << 2;     // W tile load map
    const float* Ap = A + (size_t)(m0 + lam) * K + lak;
    const float* Wp = W + (size_t)lwk * N + (n0 + lwn);

    float acc[4][4] = {};
    for (int k0 = 0; k0 < K; k0 += 16) {
        float4 av = *(const float4*)(Ap + k0);
        float4 wv = *(const float4*)(Wp + (size_t)k0 * N);
        As[lak + 0][lam] = av.x;
        As[lak + 1][lam] = av.y;
        As[lak + 2][lam] = av.z;
        As[lak + 3][lam] = av.w;
        *(float4*)&Ws[lwk][lwn] = wv;
        __syncthreads();
#pragma unroll
        for (int kk = 0; kk < 16; kk++) {
            float4 a4 = *(const float4*)&As[kk][ty << 2];
            float4 b4 = *(const float4*)&Ws[kk][tx << 2];
            float a[4] = {a4.x, a4.y, a4.z, a4.w};
            float b[4] = {b4.x, b4.y, b4.z, b4.w};
#pragma unroll
            for (int i = 0; i < 4; i++)
#pragma unroll
                for (int j = 0; j < 4; j++) acc[i][j] = fmaf(a[i], b[j], acc[i][j]);
        }
        __syncthreads();
    }

    const int n = n0 + (tx << 2);
    float4 bv = *(const float4*)(bias + n);
    float bb[4] = {bv.x, bv.y, bv.z, bv.w};
#pragma unroll
    for (int i = 0; i < 4; i++) {
        const int m = m0 + (ty << 2) + i;
        float o[4];
#pragma unroll
        for (int j = 0; j < 4; j++) o[j] = acc[i][j] + bb[j];
        if (EPI == 1) {
            float4 rv = *(const float4*)(res + (size_t)m * N + n);
            o[0] += rv.x; o[1] += rv.y; o[2] += rv.z; o[3] += rv.w;
        }
        if (EPI == 2) {
#pragma unroll
            for (int j = 0; j < 4; j++)
                o[j] = 0.5f * o[j] * (1.0f + erff(o[j] * 0.7071067811865475f));
        }
        float4 ov = make_float4(o[0], o[1], o[2], o[3]);
        *(float4*)(C + (size_t)m * N + n) = ov;
    }
}

// ---------------------------------------------------------------------------
// scores[b,h,q,k] = dot(Q[b,q,h,:], K[b,k,h,:]) / scale(b,q,k) + pb[h,q,k]
//                   + mask[b,k]
// One 64x64 tile of (q,k) per block, full DH=64 in smem (transposed: [d][row]).
// ---------------------------------------------------------------------------
__global__ void __launch_bounds__(256) scores_kernel(
    const float* __restrict__ Q, const float* __restrict__ Kt,
    const int* __restrict__ ts, const float* __restrict__ pb,
    const float* __restrict__ mask, float* __restrict__ Sc)
{
    __shared__ __align__(16) float Qs[64][68];
    __shared__ __align__(16) float Ks[64][68];
    const int tid = threadIdx.x;
    const int bh = blockIdx.z, b = bh >> 3, h = bh & 7;
    const int q0 = blockIdx.y << 6, k0 = blockIdx.x << 6;
    const int row = tid >> 2, dg = (tid & 3) << 4;
    const float* qp = Q + (size_t)(b * Sn + q0 + row) * Hn + h * DHn + dg;
    const float* kp = Kt + (size_t)(b * Sn + k0 + row) * Hn + h * DHn + dg;
#pragma unroll
    for (int c = 0; c < 4; c++) {
        const int d = dg + (c << 2);
        float4 v = *(const float4*)(qp + (c << 2));
        Qs[d + 0][row] = v.x; Qs[d + 1][row] = v.y;
        Qs[d + 2][row] = v.z; Qs[d + 3][row] = v.w;
        float4 w = *(const float4*)(kp + (c << 2));
        Ks[d + 0][row] = w.x; Ks[d + 1][row] = w.y;
        Ks[d + 2][row] = w.z; Ks[d + 3][row] = w.w;
    }
    __syncthreads();

    const int tx = tid & 15, ty = tid >> 4;
    float acc[4][4] = {};
#pragma unroll 16
    for (int d = 0; d < 64; d++) {
        float4 a4 = *(const float4*)&Qs[d][ty << 2];
        float4 b4 = *(const float4*)&Ks[d][tx << 2];
        float a[4] = {a4.x, a4.y, a4.z, a4.w};
        float b[4] = {b4.x, b4.y, b4.z, b4.w};
#pragma unroll
        for (int i = 0; i < 4; i++)
#pragma unroll
            for (int j = 0; j < 4; j++) acc[i][j] = fmaf(a[i], b[j], acc[i][j]);
    }

    int tq[4], tk[4];
    float mk[4];
#pragma unroll
    for (int i = 0; i < 4; i++) tq[i] = ts[b * Sn + q0 + (ty << 2) + i];
#pragma unroll
    for (int j = 0; j < 4; j++) {
        tk[j] = ts[b * Sn + k0 + (tx << 2) + j];
        mk[j] = mask[b * Sn + k0 + (tx << 2) + j];
    }
#pragma unroll
    for (int i = 0; i < 4; i++) {
        const int q = q0 + (ty << 2) + i;
        float4 pbv = *(const float4*)(pb + ((size_t)h * Sn + q) * Sn + k0 + (tx << 2));
        float pbb[4] = {pbv.x, pbv.y, pbv.z, pbv.w};
        float o[4];
#pragma unroll
        for (int j = 0; j < 4; j++) {
            float lag = (float)(tq[i] - tk[j]) * (1.0f / 60000.0f);
            float sc = 9.0f - 1.0f / (fmaxf(lag, 0.0f) + 1.0f);
            o[j] = acc[i][j] / sc + pbb[j] + mk[j];
        }
        float4 ov = make_float4(o[0], o[1], o[2], o[3]);
        *(float4*)(Sc + ((size_t)bh * Sn + q) * Sn + k0 + (tx << 2)) = ov;
    }
}

// ---------------------------------------------------------------------------
// Row softmax over last axis (Sn = 2048), in place. One block per row.
// ---------------------------------------------------------------------------
__global__ void __launch_bounds__(256) softmax_kernel(float* __restrict__ Sc)
{
    const size_t base = (size_t)blockIdx.x * Sn;
    const int tid = threadIdx.x;
    __shared__ float sh[8], sh2[8];
    float v[8];
    float mx = -3.4e38f;
#pragma unroll
    for (int i = 0; i < 8; i++) {
        v[i] = Sc[base + tid + (i << 8)];
        mx = fmaxf(mx, v[i]);
    }
    for (int o = 16; o; o >>= 1) mx = fmaxf(mx, __shfl_xor_sync(0xffffffffu, mx, o));
    if ((tid & 31) == 0) sh[tid >> 5] = mx;
    __syncthreads();
    mx = sh[0];
#pragma unroll
    for (int i = 1; i < 8; i++) mx = fmaxf(mx, sh[i]);

    float sum = 0.0f;
#pragma unroll
    for (int i = 0; i < 8; i++) { v[i] = expf(v[i] - mx); sum += v[i]; }
    for (int o = 16; o; o >>= 1) sum += __shfl_xor_sync(0xffffffffu, sum, o);
    if ((tid & 31) == 0) sh2[tid >> 5] = sum;
    __syncthreads();
    sum = 0.0f;
#pragma unroll
    for (int i = 0; i < 8; i++) sum += sh2[i];
    const float inv = 1.0f / sum;
#pragma unroll
    for (int i = 0; i < 8; i++) Sc[base + tid + (i << 8)] = v[i] * inv;
}

// ---------------------------------------------------------------------------
// ctx[b,q,h,d] = sum_k P[b,h,q,k] * V[b,k,h,d].  Per (b,h): M=2048,N=64,K=2048.
// 64(q) x 64(d) tile per block, K chunks of 32.
// ---------------------------------------------------------------------------
__global__ void __launch_bounds__(256) ctx_kernel(
    const float* __restrict__ P, const float* __restrict__ V, float* __restrict__ C)
{
    __shared__ __align__(16) float Ps[32][68];
    __shared__ __align__(16) float Vs[32][68];
    const int tid = threadIdx.x;
    const int bh = blockIdx.y, b = bh >> 3, h = bh & 7;
    const int q0 = blockIdx.x << 6;
    const int tx = tid & 15, ty = tid >> 4;
    const int lq = tid >> 2, lk = (tid & 3) << 3;
    const int vk = tid >> 3, vd = (tid & 7) << 3;
    const float* Pbase = P + ((size_t)bh * Sn + q0 + lq) * Sn + lk;
    const float* Vbase = V + (size_t)(b * Sn + vk) * Hn + h * DHn + vd;

    float acc[4][4] = {};
    for (int kc = 0; kc < Sn; kc += 32) {
        float4 p0 = *(const float4*)(Pbase + kc);
        float4 p1 = *(const float4*)(Pbase + kc + 4);
        Ps[lk + 0][lq] = p0.x; Ps[lk + 1][lq] = p0.y;
        Ps[lk + 2][lq] = p0.z; Ps[lk + 3][lq] = p0.w;
        Ps[lk + 4][lq] = p1.x; Ps[lk + 5][lq] = p1.y;
        Ps[lk + 6][lq] = p1.z; Ps[lk + 7][lq] = p1.w;
        const float* vp = Vbase + (size_t)kc * Hn;
        *(float4*)&Vs[vk][vd] = *(const float4*)vp;
        *(float4*)&Vs[vk][vd + 4] = *(const float4*)(vp + 4);
        __syncthreads();
#pragma unroll
        for (int kk = 0; kk < 32; kk++) {
            float4 a4 = *(const float4*)&Ps[kk][ty << 2];
            float4 b4 = *(const float4*)&Vs[kk][tx << 2];
            float a[4] = {a4.x, a4.y, a4.z, a4.w};
            float bb[4] = {b4.x, b4.y, b4.z, b4.w};
#pragma unroll
            for (int i = 0; i < 4; i++)
#pragma unroll
                for (int j = 0; j < 4; j++) acc[i][j] = fmaf(a[i], bb[j], acc[i][j]);
        }
        __syncthreads();
    }
#pragma unroll
    for (int i = 0; i < 4; i++) {
        const int q = q0 + (ty << 2) + i;
        float4 ov = make_float4(acc[i][0], acc[i][1], acc[i][2], acc[i][3]);
        *(float4*)(C + (size_t)(b * Sn + q) * Hn + h * DHn + (tx << 2)) = ov;
    }
}

// ---------------------------------------------------------------------------
// LayerNorm over H=512, one block (256 thr) per row. in may equal out.
// ---------------------------------------------------------------------------
__global__ void __launch_bounds__(256) ln_kernel(
    const float* __restrict__ in, const float* __restrict__ g,
    const float* __restrict__ bta, float* __restrict__ out)
{
    const size_t base = (size_t)blockIdx.x * Hn;
    const int tid = threadIdx.x;
    __shared__ float sh[8], sh2[8];
    float x0 = in[base + tid], x1 = in[base + tid + 256];
    float s = x0 + x1;
    for (int o = 16; o; o >>= 1) s += __shfl_xor_sync(0xffffffffu, s, o);
    if ((tid & 31) == 0) sh[tid >> 5] = s;
    __syncthreads();
    s = 0.0f;
#pragma unroll
    for (int i = 0; i < 8; i++) s += sh[i];
    const float mean = s * (1.0f / Hn);
    const float d0 = x0 - mean, d1 = x1 - mean;
    float vv = d0 * d0 + d1 * d1;
    for (int o = 16; o; o >>= 1) vv += __shfl_xor_sync(0xffffffffu, vv, o);
    if ((tid & 31) == 0) sh2[tid >> 5] = vv;
    __syncthreads();
    vv = 0.0f;
#pragma unroll
    for (int i = 0; i < 8; i++) vv += sh2[i];
    const float inv = rsqrtf(vv * (1.0f / Hn) + 1e-12f);
    out[base + tid] = d0 * inv * g[tid] + bta[tid];
    out[base + tid + 256] = d1 * inv * g[tid + 256] + bta[tid + 256];
}

// ---------------------------------------------------------------------------
extern "C" void kernel_launch(void* const* d_in, const int* in_sizes, int n_in,
                              void* d_out, int out_size)
{
    (void)in_sizes; (void)n_in; (void)out_size;
    const float* qs   = (const float*)d_in[0];
    const float* mask = (const float*)d_in[1];
    const float* pb   = (const float*)d_in[2];
    const int*   ts   = (const int*)d_in[3];
    const float* wq  = (const float*)d_in[4];  const float* bq  = (const float*)d_in[5];
    const float* wk  = (const float*)d_in[6];  const float* bk  = (const float*)d_in[7];
    const float* wv  = (const float*)d_in[8];  const float* bv  = (const float*)d_in[9];
    const float* wo  = (const float*)d_in[10]; const float* bo  = (const float*)d_in[11];
    const float* l1g = (const float*)d_in[12]; const float* l1b = (const float*)d_in[13];
    const float* wi  = (const float*)d_in[14]; const float* bi  = (const float*)d_in[15];
    const float* wo2 = (const float*)d_in[16]; const float* bo2 = (const float*)d_in[17];
    const float* l2g = (const float*)d_in[18]; const float* l2b = (const float*)d_in[19];

    float *x, *q, *k, *v, *ctx, *attn, *ffn, *sc;
    cudaGetSymbolAddress((void**)&x,    g_x);
    cudaGetSymbolAddress((void**)&q,    g_q);
    cudaGetSymbolAddress((void**)&k,    g_k);
    cudaGetSymbolAddress((void**)&v,    g_v);
    cudaGetSymbolAddress((void**)&ctx,  g_ctx);
    cudaGetSymbolAddress((void**)&attn, g_attn);
    cudaGetSymbolAddress((void**)&ffn,  g_ffn);
    cudaGetSymbolAddress((void**)&sc,   g_sc);

    cudaMemcpyAsync(x, qs, sizeof(float) * (size_t)Mn * Hn,
                    cudaMemcpyDeviceToDevice, 0);

    dim3 gproj(Hn / 64, Mn / 64);          // (8, 128)
    dim3 gff(Fn / 64, Mn / 64);            // (32, 128)
    dim3 gsc(Sn / 64, Sn / 64, Bn * NHn);  // (32, 32, 32)
    dim3 gctx(Sn / 64, Bn * NHn);          // (32, 32)

    for (int l = 0; l < Ln; l++) {
        const size_t wOff  = (size_t)l * Hn * Hn;
        const size_t bOff  = (size_t)l * Hn;
        const size_t wiOff = (size_t)l * Hn * Fn;
        const size_t biOff = (size_t)l * Fn;

        gemm_kernel<0><<<gproj, 256>>>(x, wq + wOff, bq + bOff, nullptr, q, Hn, Hn);
        gemm_kernel<0><<<gproj, 256>>>(x, wk + wOff, bk + bOff, nullptr, k, Hn, Hn);
        gemm_kernel<0><<<gproj, 256>>>(x, wv + wOff, bv + bOff, nullptr, v, Hn, Hn);

        scores_kernel<<<gsc, 256>>>(q, k, ts, pb, mask, sc);
        softmax_kernel<<<Bn * NHn * Sn, 256>>>(sc);
        ctx_kernel<<<gctx, 256>>>(sc, v, ctx);

        gemm_kernel<1><<<gproj, 256>>>(ctx, wo + wOff, bo + bOff, x, attn, Hn, Hn);
        ln_kernel<<<Mn, 256>>>(attn, l1g + bOff, l1b + bOff, attn);

        gemm_kernel<2><<<gff, 256>>>(attn, wi + wiOff, bi + biOff, nullptr, ffn, Hn, Fn);
        gemm_kernel<1><<<gproj, 256>>>(ffn, wo2 + wiOff, bo2 + bOff, attn, x, Fn, Hn);

        float* lnout = (l == Ln - 1) ? (float*)d_out : x;
        ln_kernel<<<Mn, 256>>>(x, l2g + bOff, l2b + bOff, lnout);
    }
}